// round 2
// baseline (speedup 1.0000x reference)
#include <cuda_runtime.h>
#include <cstdint>

#define NTOT 32768          // 32*32*32
#define C 64
#define REG 2097152         // per-tensor region in g_qk: 4 heads * 32768 * 16

// ---------------- scratch (static device memory; no allocation) ----------------
__device__ float g_ln[C * NTOT];        // layernorm output, (C,N)
__device__ float g_qk[4 * REG];         // [qT | kT | vsaT | vca]
__device__ float g_sa[REG];             // x_sa flat [h][n][d] == (N,C) view
__device__ float g_skip[C * NTOT];      // attention output / residual, (C,N)
__device__ float g_t1[C * NTOT];
__device__ float g_t2[C * NTOT];
__device__ float g_t3[C * NTOT];
__device__ float g_gpart[1024 * 128];   // per-chunk Gram partials [h*256+de][chunk]
__device__ float g_nqpart[64 * 128];
__device__ float g_nkpart[64 * 128];
__device__ float g_A[1024];             // channel attention [h][d][e]
__device__ float g_bn[128];             // mean[64], rstd[64]

// ---------------- f32x2 packed math (sm_100+) ----------------
__device__ __forceinline__ unsigned long long pack2(float a, float b) {
    unsigned long long r;
    asm("mov.b64 %0, {%1, %2};" : "=l"(r) : "f"(a), "f"(b));
    return r;
}
__device__ __forceinline__ void unpack2(unsigned long long v, float& a, float& b) {
    asm("mov.b64 {%0, %1}, %2;" : "=f"(a), "=f"(b) : "l"(v));
}
__device__ __forceinline__ void ffma2(unsigned long long& d, unsigned long long a, unsigned long long b) {
    asm("fma.rn.f32x2 %0, %1, %2, %0;" : "+l"(d) : "l"(a), "l"(b));
}

// ---------------- 1) LayerNorm over C, (C,N)->(C,N) ----------------
__global__ void k_layernorm(const float* __restrict__ x, const float* __restrict__ g,
                            const float* __restrict__ b) {
    int n = blockIdx.x * 256 + threadIdx.x;
    float v[C];
    float s = 0.f, ss = 0.f;
#pragma unroll
    for (int c = 0; c < C; c++) {
        float t = x[c * NTOT + n];
        v[c] = t; s += t; ss += t * t;
    }
    float m = s * (1.f / C);
    float var = ss * (1.f / C) - m * m;
    float rstd = rsqrtf(var + 1e-5f);
#pragma unroll
    for (int c = 0; c < C; c++)
        g_ln[c * NTOT + n] = (v[c] - m) * rstd * __ldg(&g[c]) + __ldg(&b[c]);
}

// ---------------- 2) qkvv GEMM (256x64)@(64,N), writes transposed layouts -------
// slab = blockIdx.y in [0,16): rows [slab*16, slab*16+16). type=slab/4, h=slab%4.
// q/k/v_sa -> [h][n][16d] regions; v_ca -> (row, n) region.
__global__ void k_qkvv(const float* __restrict__ W) {
    __shared__ float xs[8][1024];
    __shared__ float ws[16][8];
    int slab = blockIdx.y;
    int nb = blockIdx.x * 1024;
    int tid = threadIdx.x;
    float acc[4][16];
#pragma unroll
    for (int p = 0; p < 4; p++)
#pragma unroll
        for (int r = 0; r < 16; r++) acc[p][r] = 0.f;

    for (int cc = 0; cc < 8; cc++) {
#pragma unroll
        for (int l = 0; l < 32; l++) {
            int idx = tid + l * 256;
            int c8 = idx >> 10, nn = idx & 1023;
            xs[c8][nn] = g_ln[(cc * 8 + c8) * NTOT + nb + nn];
        }
        if (tid < 128) {
            int r = tid >> 3, c8 = tid & 7;
            ws[r][c8] = W[(slab * 16 + r) * 64 + cc * 8 + c8];
        }
        __syncthreads();
#pragma unroll
        for (int c8 = 0; c8 < 8; c8++) {
            float xv[4];
#pragma unroll
            for (int p = 0; p < 4; p++) xv[p] = xs[c8][tid + p * 256];
#pragma unroll
            for (int r = 0; r < 16; r++) {
                float wv = ws[r][c8];
#pragma unroll
                for (int p = 0; p < 4; p++) acc[p][r] += xv[p] * wv;
            }
        }
        __syncthreads();
    }
    int type = slab >> 2, h = slab & 3;
    if (type == 2) {  // v_ca: (row, n) layout at region 3
#pragma unroll
        for (int p = 0; p < 4; p++) {
            int n = nb + tid + p * 256;
#pragma unroll
            for (int r = 0; r < 16; r++)
                g_qk[(size_t)3 * REG + (h * 16 + r) * NTOT + n] = acc[p][r];
        }
    } else {
        size_t roff = (type == 0) ? 0 : (type == 1) ? (size_t)REG : (size_t)2 * REG;
#pragma unroll
        for (int p = 0; p < 4; p++) {
            int n = nb + tid + p * 256;
            float4* dst = reinterpret_cast<float4*>(g_qk + roff + (size_t)(h * NTOT + n) * 16);
#pragma unroll
            for (int q4 = 0; q4 < 4; q4++)
                dst[q4] = make_float4(acc[p][q4 * 4], acc[p][q4 * 4 + 1],
                                      acc[p][q4 * 4 + 2], acc[p][q4 * 4 + 3]);
        }
    }
}

// ---------------- 3) channel attention Gram partials (deterministic) -------------
__global__ void k_gram() {
    __shared__ float qs[256][17];
    __shared__ float ks[256][17];
    int h = blockIdx.y, chunk = blockIdx.x, t = threadIdx.x;
    int n = chunk * 256 + t;
    const float4* qp = reinterpret_cast<const float4*>(g_qk + (size_t)(h * NTOT + n) * 16);
    const float4* kp = reinterpret_cast<const float4*>(g_qk + REG + (size_t)(h * NTOT + n) * 16);
#pragma unroll
    for (int i = 0; i < 4; i++) {
        float4 a = qp[i], b = kp[i];
        qs[t][i * 4 + 0] = a.x; qs[t][i * 4 + 1] = a.y; qs[t][i * 4 + 2] = a.z; qs[t][i * 4 + 3] = a.w;
        ks[t][i * 4 + 0] = b.x; ks[t][i * 4 + 1] = b.y; ks[t][i * 4 + 2] = b.z; ks[t][i * 4 + 3] = b.w;
    }
    __syncthreads();
    int d = t >> 4, e = t & 15;
    float acc = 0.f;
    for (int j = 0; j < 256; j++) acc += qs[j][d] * ks[j][e];
    g_gpart[(h * 256 + t) * 128 + chunk] = acc;
    if (t < 16) {
        float s = 0.f;
        for (int j = 0; j < 256; j++) s += qs[j][t] * qs[j][t];
        g_nqpart[(h * 16 + t) * 128 + chunk] = s;
    } else if (t < 32) {
        int dd = t - 16;
        float s = 0.f;
        for (int j = 0; j < 256; j++) s += ks[j][dd] * ks[j][dd];
        g_nkpart[(h * 16 + dd) * 128 + chunk] = s;
    }
}

// ---------------- 4) finalize channel attention softmax ----------------
__global__ void k_ca_fin(const float* __restrict__ temp) {
    __shared__ float Gs[1024];
    __shared__ float nqs[64];
    __shared__ float nks[64];
    int t = threadIdx.x;  // 64 threads
    for (int r = t; r < 1024; r += 64) {
        float s = 0.f;
        for (int j = 0; j < 128; j++) s += g_gpart[r * 128 + j];
        Gs[r] = s;
    }
    {
        float s = 0.f;
        for (int j = 0; j < 128; j++) s += g_nqpart[t * 128 + j];
        nqs[t] = fmaxf(sqrtf(s), 1e-12f);
        float s2 = 0.f;
        for (int j = 0; j < 128; j++) s2 += g_nkpart[t * 128 + j];
        nks[t] = fmaxf(sqrtf(s2), 1e-12f);
    }
    __syncthreads();
    int h = t >> 4, d = t & 15;
    float tp = __ldg(&temp[h]);
    float dq = nqs[t];
    float row[16], mx = -1e30f;
#pragma unroll
    for (int e = 0; e < 16; e++) {
        row[e] = Gs[h * 256 + d * 16 + e] / (dq * nks[h * 16 + e]) * tp;
        mx = fmaxf(mx, row[e]);
    }
    float sum = 0.f;
#pragma unroll
    for (int e = 0; e < 16; e++) { row[e] = __expf(row[e] - mx); sum += row[e]; }
    float inv = 1.f / sum;
#pragma unroll
    for (int e = 0; e < 16; e++) g_A[h * 256 + d * 16 + e] = row[e] * inv;
}

// ---------------- 5) spatial (local window) attention ----------------
__global__ void k_spatial(const float* __restrict__ qemb, const float* __restrict__ temp2,
                          const float* __restrict__ rpb) {
    int n = blockIdx.x * 256 + threadIdx.x;
    int h = blockIdx.y;
    const float4* qp = reinterpret_cast<const float4*>(g_qk + (size_t)(h * NTOT + n) * 16);
    float q[16];
#pragma unroll
    for (int i = 0; i < 4; i++) {
        float4 v = qp[i];
        q[i * 4 + 0] = v.x; q[i * 4 + 1] = v.y; q[i * 4 + 2] = v.z; q[i * 4 + 3] = v.w;
    }
    float ssq = 0.f;
#pragma unroll
    for (int d = 0; d < 16; d++) ssq += q[d] * q[d];
    float inv = 1.f / fmaxf(sqrtf(ssq), 1e-12f);
    float sp = log1pf(expf(__ldg(&temp2[h])));
    float qn[16];
#pragma unroll
    for (int d = 0; d < 16; d++) qn[d] = (q[d] * inv + __ldg(&qemb[h * 16 + d])) * sp;

    int a0 = n >> 10, a1 = (n >> 5) & 31, a2 = n & 31;
    float sc[27];
    float mx = -1e30f;
#pragma unroll
    for (int kk = 0; kk < 27; kk++) {
        int di = kk / 9 - 1, dj = (kk / 3) % 3 - 1, dk = kk % 3 - 1;
        int b0 = a0 + di, b1 = a1 + dj, b2 = a2 + dk;
        float s = -1e30f;
        if ((unsigned)(b0 | b1 | b2) < 32u) {
            int n2 = (b0 * 32 + b1) * 32 + b2;
            const float4* kp = reinterpret_cast<const float4*>(g_qk + REG + (size_t)(h * NTOT + n2) * 16);
            float dot = 0.f;
#pragma unroll
            for (int i = 0; i < 4; i++) {
                float4 kv = kp[i];
                dot += qn[i * 4 + 0] * kv.x + qn[i * 4 + 1] * kv.y +
                       qn[i * 4 + 2] * kv.z + qn[i * 4 + 3] * kv.w;
            }
            s = dot + __ldg(&rpb[h * 27 + kk]);
        }
        sc[kk] = s;
        mx = fmaxf(mx, s);
    }
    float sum = 0.f;
#pragma unroll
    for (int kk = 0; kk < 27; kk++) { sc[kk] = __expf(sc[kk] - mx); sum += sc[kk]; }
    float rinv = 1.f / sum;
    float out[16];
#pragma unroll
    for (int d = 0; d < 16; d++) out[d] = 0.f;
#pragma unroll
    for (int kk = 0; kk < 27; kk++) {
        int di = kk / 9 - 1, dj = (kk / 3) % 3 - 1, dk = kk % 3 - 1;
        int b0 = a0 + di, b1 = a1 + dj, b2 = a2 + dk;
        if ((unsigned)(b0 | b1 | b2) < 32u) {
            int n2 = (b0 * 32 + b1) * 32 + b2;
            float p = sc[kk] * rinv;
            const float4* vp = reinterpret_cast<const float4*>(g_qk + (size_t)2 * REG + (size_t)(h * NTOT + n2) * 16);
#pragma unroll
            for (int i = 0; i < 4; i++) {
                float4 vv = vp[i];
                out[i * 4 + 0] += p * vv.x; out[i * 4 + 1] += p * vv.y;
                out[i * 4 + 2] += p * vv.z; out[i * 4 + 3] += p * vv.w;
            }
        }
    }
    float4* dst = reinterpret_cast<float4*>(g_sa + (size_t)(h * NTOT + n) * 16);
#pragma unroll
    for (int i = 0; i < 4; i++)
        dst[i] = make_float4(out[i * 4], out[i * 4 + 1], out[i * 4 + 2], out[i * 4 + 3]);
}

// ---------------- 6) combine: projections + residual -> skip (C,N) -------------
__global__ void k_combine(const float* __restrict__ x, const float* __restrict__ gamma,
                          const float* __restrict__ w1, const float* __restrict__ b1,
                          const float* __restrict__ w2, const float* __restrict__ b2) {
    __shared__ float w1s[2048];
    __shared__ float w2s[2048];
    __shared__ float As[1024];
    __shared__ float b1s[32];
    __shared__ float b2s[32];
    int t = threadIdx.x;
    for (int i = t; i < 2048; i += 256) { w1s[i] = w1[i]; w2s[i] = w2[i]; }
    for (int i = t; i < 1024; i += 256) As[i] = g_A[i];
    if (t < 32) { b1s[t] = b1[t]; b2s[t] = b2[t]; }
    __syncthreads();
    int n = blockIdx.x * 256 + t;
    // phase A: x_sa -> op1
    {
        float xsa[64];
        const float4* sp4 = reinterpret_cast<const float4*>(g_sa + (size_t)n * 64);
#pragma unroll
        for (int i = 0; i < 16; i++) {
            float4 v = sp4[i];
            xsa[i * 4 + 0] = v.x; xsa[i * 4 + 1] = v.y; xsa[i * 4 + 2] = v.z; xsa[i * 4 + 3] = v.w;
        }
        for (int o = 0; o < 32; o++) {
            float a = b1s[o];
#pragma unroll
            for (int c = 0; c < 64; c++) a += xsa[c] * w1s[o * 64 + c];
            g_skip[o * NTOT + n] = x[o * NTOT + n] + __ldg(&gamma[o]) * a;
        }
    }
    // phase B: x_ca -> op2
    {
        float xca[64];
#pragma unroll
        for (int h = 0; h < 4; h++) {
            float vc[16];
#pragma unroll
            for (int e = 0; e < 16; e++)
                vc[e] = g_qk[(size_t)3 * REG + (h * 16 + e) * NTOT + n];
#pragma unroll
            for (int d = 0; d < 16; d++) {
                float a = 0.f;
#pragma unroll
                for (int e = 0; e < 16; e++) a += As[h * 256 + d * 16 + e] * vc[e];
                xca[h * 16 + d] = a;
            }
        }
        for (int o = 0; o < 32; o++) {
            float a = b2s[o];
#pragma unroll
            for (int c = 0; c < 64; c++) a += xca[c] * w2s[o * 64 + c];
            g_skip[(32 + o) * NTOT + n] = x[(32 + o) * NTOT + n] + __ldg(&gamma[32 + o]) * a;
        }
    }
}

// ---------------- 7) conv3d 3x3x3 pad 1, 64->64, f32x2 packed ----------------
// grid (32, 4): 32 spatial tiles (a0 step 4, a1 step 8, full a2), 4 o-groups of 16
__global__ void k_conv3(const float* __restrict__ in, const float* __restrict__ w,
                        const float* __restrict__ bias, float* __restrict__ out) {
    __shared__ float xs[4 * 2040];   // 4 i x 6 x 10 x 34 halo tile
    __shared__ float2 ws[1728];      // 16 o x 4 i x 27, duplicated pairs
    int tid = threadIdx.x;
    int tile = blockIdx.x;
    int a0b = (tile >> 2) * 4, a1b = (tile & 3) * 8;
    int obase = blockIdx.y * 16;

    int pbase[4], nout[4];
#pragma unroll
    for (int p = 0; p < 4; p++) {
        int sp = tid + p * 256;
        int z = sp >> 8, y = (sp >> 5) & 7, xx = sp & 31;
        pbase[p] = z * 340 + y * 34 + xx;
        nout[p] = (a0b + z) * 1024 + (a1b + y) * 32 + xx;
    }
    unsigned long long acc01[16], acc23[16];
#pragma unroll
    for (int o = 0; o < 16; o++) { acc01[o] = 0ull; acc23[o] = 0ull; }

    for (int ci = 0; ci < 16; ci++) {
        int ibase = ci * 4;
        for (int idx = tid; idx < 8160; idx += 256) {
            int ii = idx / 2040;
            int r1 = idx - ii * 2040;
            int zz = r1 / 340;
            int r2 = r1 - zz * 340;
            int yy = r2 / 34;
            int xxx = r2 - yy * 34;
            int ga0 = a0b + zz - 1, ga1 = a1b + yy - 1, ga2 = xxx - 1;
            float v = 0.f;
            if ((unsigned)(ga0 | ga1 | ga2) < 32u)
                v = in[(ibase + ii) * NTOT + ga0 * 1024 + ga1 * 32 + ga2];
            xs[idx] = v;
        }
        for (int idx = tid; idx < 1728; idx += 256) {
            int o = idx / 108;
            int r = idx - o * 108;
            int ii = r / 27, kk = r - ii * 27;
            float wv = w[(obase + o) * 1728 + (ibase + ii) * 27 + kk];
            ws[idx] = make_float2(wv, wv);
        }
        __syncthreads();
#pragma unroll
        for (int ii = 0; ii < 4; ii++) {
#pragma unroll
            for (int kk = 0; kk < 27; kk++) {
                int koff = (kk / 9) * 340 + ((kk / 3) % 3) * 34 + (kk % 3);
                int xb = ii * 2040 + koff;
                unsigned long long x01 = pack2(xs[xb + pbase[0]], xs[xb + pbase[1]]);
                unsigned long long x23 = pack2(xs[xb + pbase[2]], xs[xb + pbase[3]]);
#pragma unroll
                for (int o = 0; o < 16; o++) {
                    unsigned long long wv =
                        *reinterpret_cast<const unsigned long long*>(&ws[o * 108 + ii * 27 + kk]);
                    ffma2(acc01[o], x01, wv);
                    ffma2(acc23[o], x23, wv);
                }
            }
        }
        __syncthreads();
    }
#pragma unroll
    for (int o = 0; o < 16; o++) {
        float bo = __ldg(&bias[obase + o]);
        float f0, f1, f2, f3;
        unpack2(acc01[o], f0, f1);
        unpack2(acc23[o], f2, f3);
        size_t ob = (size_t)(obase + o) * NTOT;
        out[ob + nout[0]] = f0 + bo;
        out[ob + nout[1]] = f1 + bo;
        out[ob + nout[2]] = f2 + bo;
        out[ob + nout[3]] = f3 + bo;
    }
}

// ---------------- 8) batchnorm stats (training-mode, biased var) ----------------
__global__ void k_bnstats(const float* __restrict__ t) {
    __shared__ float rs[256];
    __shared__ float rss[256];
    int c = blockIdx.x, tid = threadIdx.x;
    float s = 0.f, ss = 0.f;
    for (int i = tid; i < NTOT; i += 256) {
        float v = t[c * NTOT + i];
        s += v; ss += v * v;
    }
    rs[tid] = s; rss[tid] = ss;
    __syncthreads();
    for (int off = 128; off > 0; off >>= 1) {
        if (tid < off) { rs[tid] += rs[tid + off]; rss[tid] += rss[tid + off]; }
        __syncthreads();
    }
    if (tid == 0) {
        float m = rs[0] * (1.f / NTOT);
        float var = rss[0] * (1.f / NTOT) - m * m;
        g_bn[c] = m;
        g_bn[64 + c] = rsqrtf(var + 1e-5f);
    }
}

// ---------------- 9) bn apply (+optional residual) + leaky relu ----------------
__global__ void k_bnapply(const float* __restrict__ t, const float* __restrict__ g,
                          const float* __restrict__ be, const float* __restrict__ res,
                          float* __restrict__ out) {
    int idx = blockIdx.x * 256 + threadIdx.x;
    int c = idx >> 15;
    float v = (t[idx] - g_bn[c]) * g_bn[64 + c] * __ldg(&g[c]) + __ldg(&be[c]);
    if (res) v += res[idx];
    out[idx] = v > 0.f ? v : 0.01f * v;
}

// ---------------- 10) final: out = skip + conv1x1(y) ----------------
__global__ void k_final(const float* __restrict__ skip, const float* __restrict__ y,
                        const float* __restrict__ cw, const float* __restrict__ cb,
                        float* __restrict__ out) {
    __shared__ float ws[4096];
    int t = threadIdx.x;
    for (int i = t; i < 4096; i += 256) ws[i] = cw[i];
    __syncthreads();
    int n = blockIdx.x * 256 + t;
    float yv[64];
#pragma unroll
    for (int i = 0; i < 64; i++) yv[i] = y[i * NTOT + n];
    for (int c = 0; c < 64; c++) {
        float a = __ldg(&cb[c]);
#pragma unroll
        for (int i = 0; i < 64; i++) a += ws[c * 64 + i] * yv[i];
        out[c * NTOT + n] = skip[c * NTOT + n] + a;
    }
}

// ---------------- launch ----------------
extern "C" void kernel_launch(void* const* d_in, const int* in_sizes, int n_in,
                              void* d_out, int out_size) {
    const float* x      = (const float*)d_in[0];
    const float* ln_g   = (const float*)d_in[1];
    const float* ln_b   = (const float*)d_in[2];
    const float* gamma  = (const float*)d_in[3];
    const float* qkvv_w = (const float*)d_in[4];
    const float* temp   = (const float*)d_in[5];
    const float* temp2  = (const float*)d_in[6];
    const float* rpb    = (const float*)d_in[7];
    const float* qemb   = (const float*)d_in[8];
    const float* op1_w  = (const float*)d_in[9];
    const float* op1_b  = (const float*)d_in[10];
    const float* op2_w  = (const float*)d_in[11];
    const float* op2_b  = (const float*)d_in[12];
    const float* c51_w1 = (const float*)d_in[13];
    const float* c51_b1 = (const float*)d_in[14];
    const float* c51_g1 = (const float*)d_in[15];
    const float* c51_be1= (const float*)d_in[16];
    const float* c51_w2 = (const float*)d_in[17];
    const float* c51_b2 = (const float*)d_in[18];
    const float* c51_g2 = (const float*)d_in[19];
    const float* c51_be2= (const float*)d_in[20];
    const float* c52_w1 = (const float*)d_in[21];
    const float* c52_b1 = (const float*)d_in[22];
    const float* c52_g1 = (const float*)d_in[23];
    const float* c52_be1= (const float*)d_in[24];
    const float* c52_w2 = (const float*)d_in[25];
    const float* c52_b2 = (const float*)d_in[26];
    const float* c52_g2 = (const float*)d_in[27];
    const float* c52_be2= (const float*)d_in[28];
    const float* c8_w   = (const float*)d_in[29];
    const float* c8_b   = (const float*)d_in[30];
    float* out = (float*)d_out;

    float *p_skip, *p_t1, *p_t2, *p_t3;
    cudaGetSymbolAddress((void**)&p_skip, g_skip);
    cudaGetSymbolAddress((void**)&p_t1, g_t1);
    cudaGetSymbolAddress((void**)&p_t2, g_t2);
    cudaGetSymbolAddress((void**)&p_t3, g_t3);

    k_layernorm<<<128, 256>>>(x, ln_g, ln_b);
    k_qkvv<<<dim3(32, 16), 256>>>(qkvv_w);
    k_gram<<<dim3(128, 4), 256>>>();
    k_ca_fin<<<1, 64>>>(temp);
    k_spatial<<<dim3(128, 4), 256>>>(qemb, temp2, rpb);
    k_combine<<<128, 256>>>(x, gamma, op1_w, op1_b, op2_w, op2_b);

    // resblock 1
    k_conv3<<<dim3(32, 4), 256>>>(p_skip, c51_w1, c51_b1, p_t1);
    k_bnstats<<<64, 256>>>(p_t1);
    k_bnapply<<<8192, 256>>>(p_t1, c51_g1, c51_be1, nullptr, p_t2);
    k_conv3<<<dim3(32, 4), 256>>>(p_t2, c51_w2, c51_b2, p_t1);
    k_bnstats<<<64, 256>>>(p_t1);
    k_bnapply<<<8192, 256>>>(p_t1, c51_g2, c51_be2, p_skip, p_t3);

    // resblock 2
    k_conv3<<<dim3(32, 4), 256>>>(p_t3, c52_w1, c52_b1, p_t1);
    k_bnstats<<<64, 256>>>(p_t1);
    k_bnapply<<<8192, 256>>>(p_t1, c52_g1, c52_be1, nullptr, p_t2);
    k_conv3<<<dim3(32, 4), 256>>>(p_t2, c52_w2, c52_b2, p_t1);
    k_bnstats<<<64, 256>>>(p_t1);
    k_bnapply<<<8192, 256>>>(p_t1, c52_g2, c52_be2, p_t3, p_t2);

    k_final<<<128, 256>>>(p_skip, p_t2, c8_w, c8_b, out);
}

// round 3
// speedup vs baseline: 1.5326x; 1.5326x over previous
#include <cuda_runtime.h>
#include <cstdint>

#define NTOT 32768          // 32*32*32
#define C 64
#define REG 2097152         // per-tensor region in g_qk: 4 heads * 32768 * 16
#define SPP 817             // spatial smem plane pitch (float4 units)

// ---------------- scratch (static device memory; no allocation) ----------------
__device__ float g_ln[C * NTOT];        // layernorm output, (C,N)
__device__ float g_qk[4 * REG];         // [qT | kT | vsaT | vca]
__device__ float g_sa[REG];             // x_sa flat [h][n][d] == (N,C) view
__device__ float g_skip[C * NTOT];      // attention output / residual, (C,N)
__device__ float g_t1[C * NTOT];
__device__ float g_t2[C * NTOT];
__device__ float g_t3[C * NTOT];
__device__ float g_gpart[1024 * 128];   // per-chunk Gram partials [h*256+de][chunk]
__device__ float g_nqpart[64 * 128];
__device__ float g_nkpart[64 * 128];
__device__ float g_G[1024];
__device__ float g_nq[64];
__device__ float g_nk[64];
__device__ float g_A[1024];             // channel attention [h][d][e]
__device__ float g_bn[128];             // mean[64], rstd[64]
__device__ float g_bnps[64 * 32];       // per-tile channel sums
__device__ float g_bnpq[64 * 32];       // per-tile channel sumsq

// ---------------- f32x2 packed math (sm_100+) ----------------
__device__ __forceinline__ unsigned long long pack2(float a, float b) {
    unsigned long long r;
    asm("mov.b64 %0, {%1, %2};" : "=l"(r) : "f"(a), "f"(b));
    return r;
}
__device__ __forceinline__ void unpack2(unsigned long long v, float& a, float& b) {
    asm("mov.b64 {%0, %1}, %2;" : "=f"(a), "=f"(b) : "l"(v));
}
__device__ __forceinline__ void ffma2(unsigned long long& d, unsigned long long a, unsigned long long b) {
    asm("fma.rn.f32x2 %0, %1, %2, %0;" : "+l"(d) : "l"(a), "l"(b));
}

// ---------------- 1) LayerNorm over C, (C,N)->(C,N) ----------------
__global__ void k_layernorm(const float* __restrict__ x, const float* __restrict__ g,
                            const float* __restrict__ b) {
    int n = blockIdx.x * 256 + threadIdx.x;
    float v[C];
    float s = 0.f, ss = 0.f;
#pragma unroll
    for (int c = 0; c < C; c++) {
        float t = x[c * NTOT + n];
        v[c] = t; s += t; ss += t * t;
    }
    float m = s * (1.f / C);
    float var = ss * (1.f / C) - m * m;
    float rstd = rsqrtf(var + 1e-5f);
#pragma unroll
    for (int c = 0; c < C; c++)
        g_ln[c * NTOT + n] = (v[c] - m) * rstd * __ldg(&g[c]) + __ldg(&b[c]);
}

// ---------------- 2) qkvv GEMM (256x64)@(64,N), writes transposed layouts -------
__global__ void k_qkvv(const float* __restrict__ W) {
    __shared__ float xs[8][1024];
    __shared__ float ws[16][8];
    int slab = blockIdx.y;
    int nb = blockIdx.x * 1024;
    int tid = threadIdx.x;
    float acc[4][16];
#pragma unroll
    for (int p = 0; p < 4; p++)
#pragma unroll
        for (int r = 0; r < 16; r++) acc[p][r] = 0.f;

    for (int cc = 0; cc < 8; cc++) {
#pragma unroll
        for (int l = 0; l < 32; l++) {
            int idx = tid + l * 256;
            int c8 = idx >> 10, nn = idx & 1023;
            xs[c8][nn] = g_ln[(cc * 8 + c8) * NTOT + nb + nn];
        }
        if (tid < 128) {
            int r = tid >> 3, c8 = tid & 7;
            ws[r][c8] = W[(slab * 16 + r) * 64 + cc * 8 + c8];
        }
        __syncthreads();
#pragma unroll
        for (int c8 = 0; c8 < 8; c8++) {
            float xv[4];
#pragma unroll
            for (int p = 0; p < 4; p++) xv[p] = xs[c8][tid + p * 256];
#pragma unroll
            for (int r = 0; r < 16; r++) {
                float wv = ws[r][c8];
#pragma unroll
                for (int p = 0; p < 4; p++) acc[p][r] += xv[p] * wv;
            }
        }
        __syncthreads();
    }
    int type = slab >> 2, h = slab & 3;
    if (type == 2) {
#pragma unroll
        for (int p = 0; p < 4; p++) {
            int n = nb + tid + p * 256;
#pragma unroll
            for (int r = 0; r < 16; r++)
                g_qk[(size_t)3 * REG + (h * 16 + r) * NTOT + n] = acc[p][r];
        }
    } else {
        size_t roff = (type == 0) ? 0 : (type == 1) ? (size_t)REG : (size_t)2 * REG;
#pragma unroll
        for (int p = 0; p < 4; p++) {
            int n = nb + tid + p * 256;
            float4* dst = reinterpret_cast<float4*>(g_qk + roff + (size_t)(h * NTOT + n) * 16);
#pragma unroll
            for (int q4 = 0; q4 < 4; q4++)
                dst[q4] = make_float4(acc[p][q4 * 4], acc[p][q4 * 4 + 1],
                                      acc[p][q4 * 4 + 2], acc[p][q4 * 4 + 3]);
        }
    }
}

// ---------------- 3) channel attention Gram partials ----------------
__global__ void k_gram() {
    __shared__ float qs[256][17];
    __shared__ float ks[256][17];
    int h = blockIdx.y, chunk = blockIdx.x, t = threadIdx.x;
    int n = chunk * 256 + t;
    const float4* qp = reinterpret_cast<const float4*>(g_qk + (size_t)(h * NTOT + n) * 16);
    const float4* kp = reinterpret_cast<const float4*>(g_qk + REG + (size_t)(h * NTOT + n) * 16);
#pragma unroll
    for (int i = 0; i < 4; i++) {
        float4 a = qp[i], b = kp[i];
        qs[t][i * 4 + 0] = a.x; qs[t][i * 4 + 1] = a.y; qs[t][i * 4 + 2] = a.z; qs[t][i * 4 + 3] = a.w;
        ks[t][i * 4 + 0] = b.x; ks[t][i * 4 + 1] = b.y; ks[t][i * 4 + 2] = b.z; ks[t][i * 4 + 3] = b.w;
    }
    __syncthreads();
    int d = t >> 4, e = t & 15;
    float acc = 0.f;
    for (int j = 0; j < 256; j++) acc += qs[j][d] * ks[j][e];
    g_gpart[(h * 256 + t) * 128 + chunk] = acc;
    if (t < 16) {
        float s = 0.f;
        for (int j = 0; j < 256; j++) s += qs[j][t] * qs[j][t];
        g_nqpart[(h * 16 + t) * 128 + chunk] = s;
    } else if (t < 32) {
        int dd = t - 16;
        float s = 0.f;
        for (int j = 0; j < 256; j++) s += ks[j][dd] * ks[j][dd];
        g_nkpart[(h * 16 + dd) * 128 + chunk] = s;
    }
}

// ---------------- 3b) parallel reduce of partials ----------------
__global__ void k_careduce() {
    int r = blockIdx.x * 256 + threadIdx.x;
    if (r < 1024) {
        float s = 0.f;
#pragma unroll 8
        for (int j = 0; j < 128; j++) s += g_gpart[r * 128 + j];
        g_G[r] = s;
    } else if (r < 1088) {
        int t = r - 1024;
        float s = 0.f;
#pragma unroll 8
        for (int j = 0; j < 128; j++) s += g_nqpart[t * 128 + j];
        g_nq[t] = fmaxf(sqrtf(s), 1e-12f);
    } else if (r < 1152) {
        int t = r - 1088;
        float s = 0.f;
#pragma unroll 8
        for (int j = 0; j < 128; j++) s += g_nkpart[t * 128 + j];
        g_nk[t] = fmaxf(sqrtf(s), 1e-12f);
    }
}

// ---------------- 4) finalize channel attention softmax ----------------
__global__ void k_ca_fin(const float* __restrict__ temp) {
    int t = threadIdx.x;  // 64 threads
    int h = t >> 4, d = t & 15;
    float tp = __ldg(&temp[h]);
    float dq = g_nq[t];
    float row[16], mx = -1e30f;
#pragma unroll
    for (int e = 0; e < 16; e++) {
        row[e] = g_G[h * 256 + d * 16 + e] / (dq * g_nk[h * 16 + e]) * tp;
        mx = fmaxf(mx, row[e]);
    }
    float sum = 0.f;
#pragma unroll
    for (int e = 0; e < 16; e++) { row[e] = __expf(row[e] - mx); sum += row[e]; }
    float inv = 1.f / sum;
#pragma unroll
    for (int e = 0; e < 16; e++) g_A[h * 256 + d * 16 + e] = row[e] * inv;
}

// ---------------- 5) spatial attention, smem-tiled ----------------
// block = 256 threads = 2x4x32 positions; halo 4x6x34 = 816. k/v in dyn smem,
// layout [d4-plane][pos], plane pitch SPP=817 float4 (conflict-free phases).
__global__ void k_spatial(const float* __restrict__ qemb, const float* __restrict__ temp2,
                          const float* __restrict__ rpb) {
    extern __shared__ float4 smbuf[];
    float4* sk = smbuf;
    float4* sv = smbuf + 4 * SPP;
    int tid = threadIdx.x;
    int h = blockIdx.y;
    int z0 = (blockIdx.x >> 3) * 2, y0 = (blockIdx.x & 7) * 4;

    for (int idx = tid; idx < 3264; idx += 256) {
        int pos = idx >> 2, d4 = idx & 3;
        int hz = pos / 204;
        int rem = pos - hz * 204;
        int hy = rem / 34;
        int hx = rem - hy * 34;
        int gz = z0 + hz - 1, gy = y0 + hy - 1, gx = hx - 1;
        float4 kv = make_float4(0.f, 0.f, 0.f, 0.f);
        float4 vv = kv;
        if ((unsigned)(gz | gy | gx) < 32u) {
            int n2 = (gz * 32 + gy) * 32 + gx;
            size_t off = (size_t)(h * NTOT + n2) * 16 + d4 * 4;
            kv = *reinterpret_cast<const float4*>(g_qk + (size_t)REG + off);
            vv = *reinterpret_cast<const float4*>(g_qk + (size_t)2 * REG + off);
        }
        sk[d4 * SPP + pos] = kv;
        sv[d4 * SPP + pos] = vv;
    }

    int lx = tid & 31, ly = (tid >> 5) & 3, lz = tid >> 7;
    int gz = z0 + lz, gy = y0 + ly, gx = lx;
    int n = (gz * 32 + gy) * 32 + gx;

    float q[16];
    {
        const float4* qp = reinterpret_cast<const float4*>(g_qk + (size_t)(h * NTOT + n) * 16);
#pragma unroll
        for (int i = 0; i < 4; i++) {
            float4 v = qp[i];
            q[i * 4 + 0] = v.x; q[i * 4 + 1] = v.y; q[i * 4 + 2] = v.z; q[i * 4 + 3] = v.w;
        }
    }
    float ssq = 0.f;
#pragma unroll
    for (int d = 0; d < 16; d++) ssq += q[d] * q[d];
    float inv = 1.f / fmaxf(sqrtf(ssq), 1e-12f);
    float sp = log1pf(expf(__ldg(&temp2[h])));
    float qn[16];
#pragma unroll
    for (int d = 0; d < 16; d++) qn[d] = (q[d] * inv + __ldg(&qemb[h * 16 + d])) * sp;

    __syncthreads();

    int base = (lz + 1) * 204 + (ly + 1) * 34 + (lx + 1);
    float sc[27];
    float mx = -1e30f;
#pragma unroll
    for (int kk = 0; kk < 27; kk++) {
        int dz = kk / 9 - 1, dy = (kk / 3) % 3 - 1, dx = kk % 3 - 1;
        int bz = gz + dz, by = gy + dy, bx = gx + dx;
        float s = -1e30f;
        if ((unsigned)(bz | by | bx) < 32u) {
            int np = base + dz * 204 + dy * 34 + dx;
            float dot = 0.f;
#pragma unroll
            for (int d4 = 0; d4 < 4; d4++) {
                float4 kv = sk[d4 * SPP + np];
                dot += qn[d4 * 4 + 0] * kv.x + qn[d4 * 4 + 1] * kv.y +
                       qn[d4 * 4 + 2] * kv.z + qn[d4 * 4 + 3] * kv.w;
            }
            s = dot + __ldg(&rpb[h * 27 + kk]);
        }
        sc[kk] = s;
        mx = fmaxf(mx, s);
    }
    float sum = 0.f;
#pragma unroll
    for (int kk = 0; kk < 27; kk++) { sc[kk] = __expf(sc[kk] - mx); sum += sc[kk]; }
    float rinv = 1.f / sum;
    float out[16];
#pragma unroll
    for (int d = 0; d < 16; d++) out[d] = 0.f;
#pragma unroll
    for (int kk = 0; kk < 27; kk++) {
        int dz = kk / 9 - 1, dy = (kk / 3) % 3 - 1, dx = kk % 3 - 1;
        int bz = gz + dz, by = gy + dy, bx = gx + dx;
        if ((unsigned)(bz | by | bx) < 32u) {
            int np = base + dz * 204 + dy * 34 + dx;
            float p = sc[kk] * rinv;
#pragma unroll
            for (int d4 = 0; d4 < 4; d4++) {
                float4 vv = sv[d4 * SPP + np];
                out[d4 * 4 + 0] += p * vv.x; out[d4 * 4 + 1] += p * vv.y;
                out[d4 * 4 + 2] += p * vv.z; out[d4 * 4 + 3] += p * vv.w;
            }
        }
    }
    float4* dst = reinterpret_cast<float4*>(g_sa + (size_t)(h * NTOT + n) * 16);
#pragma unroll
    for (int i = 0; i < 4; i++)
        dst[i] = make_float4(out[i * 4], out[i * 4 + 1], out[i * 4 + 2], out[i * 4 + 3]);
}

// ---------------- 6) combine: projections + residual -> skip (C,N) -------------
__global__ void k_combine(const float* __restrict__ x, const float* __restrict__ gamma,
                          const float* __restrict__ w1, const float* __restrict__ b1,
                          const float* __restrict__ w2, const float* __restrict__ b2) {
    __shared__ float w1s[2048];
    __shared__ float w2s[2048];
    __shared__ float As[1024];
    __shared__ float b1s[32];
    __shared__ float b2s[32];
    int t = threadIdx.x;
    for (int i = t; i < 2048; i += 256) { w1s[i] = w1[i]; w2s[i] = w2[i]; }
    for (int i = t; i < 1024; i += 256) As[i] = g_A[i];
    if (t < 32) { b1s[t] = b1[t]; b2s[t] = b2[t]; }
    __syncthreads();
    int n = blockIdx.x * 256 + t;
    {
        float xsa[64];
        const float4* sp4 = reinterpret_cast<const float4*>(g_sa + (size_t)n * 64);
#pragma unroll
        for (int i = 0; i < 16; i++) {
            float4 v = sp4[i];
            xsa[i * 4 + 0] = v.x; xsa[i * 4 + 1] = v.y; xsa[i * 4 + 2] = v.z; xsa[i * 4 + 3] = v.w;
        }
        for (int o = 0; o < 32; o++) {
            float a = b1s[o];
#pragma unroll
            for (int c = 0; c < 64; c++) a += xsa[c] * w1s[o * 64 + c];
            g_skip[o * NTOT + n] = x[o * NTOT + n] + __ldg(&gamma[o]) * a;
        }
    }
    {
        float xca[64];
#pragma unroll
        for (int h = 0; h < 4; h++) {
            float vc[16];
#pragma unroll
            for (int e = 0; e < 16; e++)
                vc[e] = g_qk[(size_t)3 * REG + (h * 16 + e) * NTOT + n];
#pragma unroll
            for (int d = 0; d < 16; d++) {
                float a = 0.f;
#pragma unroll
                for (int e = 0; e < 16; e++) a += As[h * 256 + d * 16 + e] * vc[e];
                xca[h * 16 + d] = a;
            }
        }
        for (int o = 0; o < 32; o++) {
            float a = b2s[o];
#pragma unroll
            for (int c = 0; c < 64; c++) a += xca[c] * w2s[o * 64 + c];
            g_skip[(32 + o) * NTOT + n] = x[(32 + o) * NTOT + n] + __ldg(&gamma[32 + o]) * a;
        }
    }
}

// ---------------- 7) conv3d 3x3x3 pad 1, 64->64, f32x2, fused in-BN + out-stats --
// grid (32, 4): tiles (a0 step 4, a1 step 8, full a2), 4 o-groups of 16.
// fuse: input element -> bn(g_bn, bn_g, bn_be) + leaky-relu before conv.
// epilogue: per-(o,tile) sum / sumsq partials for the NEXT batchnorm.
__global__ void k_conv3(const float* __restrict__ in, const float* __restrict__ w,
                        const float* __restrict__ bias, float* __restrict__ out,
                        const float* __restrict__ bn_g, const float* __restrict__ bn_be,
                        int fuse) {
    __shared__ float xs[4 * 2040];
    __shared__ float2 ws[1728];
    __shared__ float sc4[4], sh4[4];
    __shared__ float red_s[8][16], red_q[8][16];
    int tid = threadIdx.x;
    int tile = blockIdx.x;
    int a0b = (tile >> 2) * 4, a1b = (tile & 3) * 8;
    int obase = blockIdx.y * 16;

    int pbase[4], nout[4];
#pragma unroll
    for (int p = 0; p < 4; p++) {
        int sp = tid + p * 256;
        int z = sp >> 8, y = (sp >> 5) & 7, xx = sp & 31;
        pbase[p] = z * 340 + y * 34 + xx;
        nout[p] = (a0b + z) * 1024 + (a1b + y) * 32 + xx;
    }
    unsigned long long acc01[16], acc23[16];
#pragma unroll
    for (int o = 0; o < 16; o++) { acc01[o] = 0ull; acc23[o] = 0ull; }

    for (int ci = 0; ci < 16; ci++) {
        int ibase = ci * 4;
        if (fuse && tid < 4) {
            int c = ibase + tid;
            float sc = g_bn[64 + c] * bn_g[c];
            sc4[tid] = sc;
            sh4[tid] = bn_be[c] - g_bn[c] * sc;
        }
        __syncthreads();
        for (int idx = tid; idx < 8160; idx += 256) {
            int ii = idx / 2040;
            int r1 = idx - ii * 2040;
            int zz = r1 / 340;
            int r2 = r1 - zz * 340;
            int yy = r2 / 34;
            int xxx = r2 - yy * 34;
            int ga0 = a0b + zz - 1, ga1 = a1b + yy - 1, ga2 = xxx - 1;
            float v = 0.f;
            if ((unsigned)(ga0 | ga1 | ga2) < 32u) {
                v = in[(ibase + ii) * NTOT + ga0 * 1024 + ga1 * 32 + ga2];
                if (fuse) {
                    float t = v * sc4[ii] + sh4[ii];
                    v = t > 0.f ? t : 0.01f * t;
                }
            }
            xs[idx] = v;
        }
        for (int idx = tid; idx < 1728; idx += 256) {
            int o = idx / 108;
            int r = idx - o * 108;
            int ii = r / 27, kk = r - ii * 27;
            float wv = w[(obase + o) * 1728 + (ibase + ii) * 27 + kk];
            ws[idx] = make_float2(wv, wv);
        }
        __syncthreads();
#pragma unroll
        for (int ii = 0; ii < 4; ii++) {
#pragma unroll
            for (int kk = 0; kk < 27; kk++) {
                int koff = (kk / 9) * 340 + ((kk / 3) % 3) * 34 + (kk % 3);
                int xb = ii * 2040 + koff;
                unsigned long long x01 = pack2(xs[xb + pbase[0]], xs[xb + pbase[1]]);
                unsigned long long x23 = pack2(xs[xb + pbase[2]], xs[xb + pbase[3]]);
#pragma unroll
                for (int o = 0; o < 16; o++) {
                    unsigned long long wv =
                        *reinterpret_cast<const unsigned long long*>(&ws[o * 108 + ii * 27 + kk]);
                    ffma2(acc01[o], x01, wv);
                    ffma2(acc23[o], x23, wv);
                }
            }
        }
        __syncthreads();
    }
    int lane = tid & 31, warp = tid >> 5;
#pragma unroll
    for (int o = 0; o < 16; o++) {
        float bo = __ldg(&bias[obase + o]);
        float f0, f1, f2, f3;
        unpack2(acc01[o], f0, f1);
        unpack2(acc23[o], f2, f3);
        f0 += bo; f1 += bo; f2 += bo; f3 += bo;
        size_t ob = (size_t)(obase + o) * NTOT;
        out[ob + nout[0]] = f0;
        out[ob + nout[1]] = f1;
        out[ob + nout[2]] = f2;
        out[ob + nout[3]] = f3;
        float s = f0 + f1 + f2 + f3;
        float qq = f0 * f0 + f1 * f1 + f2 * f2 + f3 * f3;
#pragma unroll
        for (int off = 16; off > 0; off >>= 1) {
            s += __shfl_down_sync(0xffffffffu, s, off);
            qq += __shfl_down_sync(0xffffffffu, qq, off);
        }
        if (lane == 0) { red_s[warp][o] = s; red_q[warp][o] = qq; }
    }
    __syncthreads();
    if (tid < 16) {
        float s = 0.f, qq = 0.f;
#pragma unroll
        for (int wp = 0; wp < 8; wp++) { s += red_s[wp][tid]; qq += red_q[wp][tid]; }
        g_bnps[(obase + tid) * 32 + blockIdx.x] = s;
        g_bnpq[(obase + tid) * 32 + blockIdx.x] = qq;
    }
}

// ---------------- 8) finalize batchnorm stats from conv partials ----------------
__global__ void k_bnfin() {
    int c = threadIdx.x;  // 64
    float s = 0.f, qq = 0.f;
#pragma unroll
    for (int j = 0; j < 32; j++) { s += g_bnps[c * 32 + j]; qq += g_bnpq[c * 32 + j]; }
    float m = s * (1.f / NTOT);
    float var = qq * (1.f / NTOT) - m * m;
    g_bn[c] = m;
    g_bn[64 + c] = rsqrtf(var + 1e-5f);
}

// ---------------- 9) bn apply + residual + leaky relu ----------------
__global__ void k_bnapply(const float* __restrict__ t, const float* __restrict__ g,
                          const float* __restrict__ be, const float* __restrict__ res,
                          float* __restrict__ out) {
    int idx = blockIdx.x * 256 + threadIdx.x;
    int c = idx >> 15;
    float v = (t[idx] - g_bn[c]) * g_bn[64 + c] * __ldg(&g[c]) + __ldg(&be[c]) + res[idx];
    out[idx] = v > 0.f ? v : 0.01f * v;
}

// ---------------- 10) final: out = skip + conv1x1(y) ----------------
__global__ void k_final(const float* __restrict__ skip, const float* __restrict__ y,
                        const float* __restrict__ cw, const float* __restrict__ cb,
                        float* __restrict__ out) {
    __shared__ float ws[4096];
    int t = threadIdx.x;
    for (int i = t; i < 4096; i += 256) ws[i] = cw[i];
    __syncthreads();
    int n = blockIdx.x * 256 + t;
    float yv[64];
#pragma unroll
    for (int i = 0; i < 64; i++) yv[i] = y[i * NTOT + n];
    for (int c = 0; c < 64; c++) {
        float a = __ldg(&cb[c]);
#pragma unroll
        for (int i = 0; i < 64; i++) a += ws[c * 64 + i] * yv[i];
        out[c * NTOT + n] = skip[c * NTOT + n] + a;
    }
}

// ---------------- launch ----------------
extern "C" void kernel_launch(void* const* d_in, const int* in_sizes, int n_in,
                              void* d_out, int out_size) {
    const float* x      = (const float*)d_in[0];
    const float* ln_g   = (const float*)d_in[1];
    const float* ln_b   = (const float*)d_in[2];
    const float* gamma  = (const float*)d_in[3];
    const float* qkvv_w = (const float*)d_in[4];
    const float* temp   = (const float*)d_in[5];
    const float* temp2  = (const float*)d_in[6];
    const float* rpb    = (const float*)d_in[7];
    const float* qemb   = (const float*)d_in[8];
    const float* op1_w  = (const float*)d_in[9];
    const float* op1_b  = (const float*)d_in[10];
    const float* op2_w  = (const float*)d_in[11];
    const float* op2_b  = (const float*)d_in[12];
    const float* c51_w1 = (const float*)d_in[13];
    const float* c51_b1 = (const float*)d_in[14];
    const float* c51_g1 = (const float*)d_in[15];
    const float* c51_be1= (const float*)d_in[16];
    const float* c51_w2 = (const float*)d_in[17];
    const float* c51_b2 = (const float*)d_in[18];
    const float* c51_g2 = (const float*)d_in[19];
    const float* c51_be2= (const float*)d_in[20];
    const float* c52_w1 = (const float*)d_in[21];
    const float* c52_b1 = (const float*)d_in[22];
    const float* c52_g1 = (const float*)d_in[23];
    const float* c52_be1= (const float*)d_in[24];
    const float* c52_w2 = (const float*)d_in[25];
    const float* c52_b2 = (const float*)d_in[26];
    const float* c52_g2 = (const float*)d_in[27];
    const float* c52_be2= (const float*)d_in[28];
    const float* c8_w   = (const float*)d_in[29];
    const float* c8_b   = (const float*)d_in[30];
    float* out = (float*)d_out;

    float *p_skip, *p_t1, *p_t2, *p_t3;
    cudaGetSymbolAddress((void**)&p_skip, g_skip);
    cudaGetSymbolAddress((void**)&p_t1, g_t1);
    cudaGetSymbolAddress((void**)&p_t2, g_t2);
    cudaGetSymbolAddress((void**)&p_t3, g_t3);

    const int SMEM_SP = 8 * SPP * 16;  // 104576 B
    cudaFuncSetAttribute(k_spatial, cudaFuncAttributeMaxDynamicSharedMemorySize, SMEM_SP);

    k_layernorm<<<128, 256>>>(x, ln_g, ln_b);
    k_qkvv<<<dim3(32, 16), 256>>>(qkvv_w);
    k_gram<<<dim3(128, 4), 256>>>();
    k_careduce<<<5, 256>>>();
    k_ca_fin<<<1, 64>>>(temp);
    k_spatial<<<dim3(128, 4), 256, SMEM_SP>>>(qemb, temp2, rpb);
    k_combine<<<128, 256>>>(x, gamma, op1_w, op1_b, op2_w, op2_b);

    // resblock 1
    k_conv3<<<dim3(32, 4), 256>>>(p_skip, c51_w1, c51_b1, p_t1, nullptr, nullptr, 0);
    k_bnfin<<<1, 64>>>();                                     // stats of t1 (conv1 out)
    k_conv3<<<dim3(32, 4), 256>>>(p_t1, c51_w2, c51_b2, p_t2, c51_g1, c51_be1, 1);
    k_bnfin<<<1, 64>>>();                                     // stats of t2 (conv2 out)
    k_bnapply<<<8192, 256>>>(p_t2, c51_g2, c51_be2, p_skip, p_t3);

    // resblock 2
    k_conv3<<<dim3(32, 4), 256>>>(p_t3, c52_w1, c52_b1, p_t1, nullptr, nullptr, 0);
    k_bnfin<<<1, 64>>>();
    k_conv3<<<dim3(32, 4), 256>>>(p_t1, c52_w2, c52_b2, p_t2, c52_g1, c52_be1, 1);
    k_bnfin<<<1, 64>>>();
    k_bnapply<<<8192, 256>>>(p_t2, c52_g2, c52_be2, p_t3, p_t1);

    k_final<<<128, 256>>>(p_skip, p_t1, c8_w, c8_b, out);
}

// round 5
// speedup vs baseline: 1.5989x; 1.0433x over previous
#include <cuda_runtime.h>
#include <cstdint>

#define NTOT 32768          // 32*32*32
#define C 64
#define REG 2097152         // per-tensor region in g_qk: 4 heads * 32768 * 16
#define SPP 817             // spatial smem plane pitch (float4 units)

// ---------------- scratch (static device memory; no allocation) ----------------
__device__ float g_ln[C * NTOT];        // layernorm output, (C,N)
__device__ float g_qk[4 * REG];         // [qT | kT | vsaT | vca]
__device__ float g_sa[REG];             // x_sa flat [h][n][d] == (N,C) view
__device__ float g_skip[C * NTOT];      // attention output / residual, (C,N)
__device__ float g_t1[C * NTOT];
__device__ float g_t2[C * NTOT];
__device__ float g_t3[C * NTOT];
__device__ float g_gpart[1024 * 128];   // per-chunk Gram partials [h*256+de][chunk]
__device__ float g_nqpart[64 * 128];
__device__ float g_nkpart[64 * 128];
__device__ float g_G[1024];
__device__ float g_nq[64];
__device__ float g_nk[64];
__device__ float g_A[1024];             // channel attention [h][d][e]
__device__ float g_bn[128];             // mean[64], rstd[64]
__device__ float g_bnps[64 * 32];       // per-tile channel sums
__device__ float g_bnpq[64 * 32];       // per-tile channel sumsq

// ---------------- f32x2 packed math (sm_100+) ----------------
__device__ __forceinline__ unsigned long long pack2(float a, float b) {
    unsigned long long r;
    asm("mov.b64 %0, {%1, %2};" : "=l"(r) : "f"(a), "f"(b));
    return r;
}
__device__ __forceinline__ void unpack2(unsigned long long v, float& a, float& b) {
    asm("mov.b64 {%0, %1}, %2;" : "=f"(a), "=f"(b) : "l"(v));
}
__device__ __forceinline__ void ffma2(unsigned long long& d, unsigned long long a, unsigned long long b) {
    asm("fma.rn.f32x2 %0, %1, %2, %0;" : "+l"(d) : "l"(a), "l"(b));
}

// ---------------- 1) LayerNorm over C, (C,N)->(C,N) ----------------
__global__ void k_layernorm(const float* __restrict__ x, const float* __restrict__ g,
                            const float* __restrict__ b) {
    int n = blockIdx.x * 256 + threadIdx.x;
    float v[C];
    float s = 0.f, ss = 0.f;
#pragma unroll
    for (int c = 0; c < C; c++) {
        float t = x[c * NTOT + n];
        v[c] = t; s += t; ss += t * t;
    }
    float m = s * (1.f / C);
    float var = ss * (1.f / C) - m * m;
    float rstd = rsqrtf(var + 1e-5f);
#pragma unroll
    for (int c = 0; c < C; c++)
        g_ln[c * NTOT + n] = (v[c] - m) * rstd * __ldg(&g[c]) + __ldg(&b[c]);
}

// ---------------- 2) qkvv GEMM ----------------
__global__ void k_qkvv(const float* __restrict__ W) {
    __shared__ float xs[8][1024];
    __shared__ float ws[16][8];
    int slab = blockIdx.y;
    int nb = blockIdx.x * 1024;
    int tid = threadIdx.x;
    float acc[4][16];
#pragma unroll
    for (int p = 0; p < 4; p++)
#pragma unroll
        for (int r = 0; r < 16; r++) acc[p][r] = 0.f;

    for (int cc = 0; cc < 8; cc++) {
#pragma unroll
        for (int l = 0; l < 32; l++) {
            int idx = tid + l * 256;
            int c8 = idx >> 10, nn = idx & 1023;
            xs[c8][nn] = g_ln[(cc * 8 + c8) * NTOT + nb + nn];
        }
        if (tid < 128) {
            int r = tid >> 3, c8 = tid & 7;
            ws[r][c8] = W[(slab * 16 + r) * 64 + cc * 8 + c8];
        }
        __syncthreads();
#pragma unroll
        for (int c8 = 0; c8 < 8; c8++) {
            float xv[4];
#pragma unroll
            for (int p = 0; p < 4; p++) xv[p] = xs[c8][tid + p * 256];
#pragma unroll
            for (int r = 0; r < 16; r++) {
                float wv = ws[r][c8];
#pragma unroll
                for (int p = 0; p < 4; p++) acc[p][r] += xv[p] * wv;
            }
        }
        __syncthreads();
    }
    int type = slab >> 2, h = slab & 3;
    if (type == 2) {
#pragma unroll
        for (int p = 0; p < 4; p++) {
            int n = nb + tid + p * 256;
#pragma unroll
            for (int r = 0; r < 16; r++)
                g_qk[(size_t)3 * REG + (h * 16 + r) * NTOT + n] = acc[p][r];
        }
    } else {
        size_t roff = (type == 0) ? 0 : (type == 1) ? (size_t)REG : (size_t)2 * REG;
#pragma unroll
        for (int p = 0; p < 4; p++) {
            int n = nb + tid + p * 256;
            float4* dst = reinterpret_cast<float4*>(g_qk + roff + (size_t)(h * NTOT + n) * 16);
#pragma unroll
            for (int q4 = 0; q4 < 4; q4++)
                dst[q4] = make_float4(acc[p][q4 * 4], acc[p][q4 * 4 + 1],
                                      acc[p][q4 * 4 + 2], acc[p][q4 * 4 + 3]);
        }
    }
}

// ---------------- 3) channel attention Gram partials ----------------
__global__ void k_gram() {
    __shared__ float qs[256][17];
    __shared__ float ks[256][17];
    int h = blockIdx.y, chunk = blockIdx.x, t = threadIdx.x;
    int n = chunk * 256 + t;
    const float4* qp = reinterpret_cast<const float4*>(g_qk + (size_t)(h * NTOT + n) * 16);
    const float4* kp = reinterpret_cast<const float4*>(g_qk + REG + (size_t)(h * NTOT + n) * 16);
#pragma unroll
    for (int i = 0; i < 4; i++) {
        float4 a = qp[i], b = kp[i];
        qs[t][i * 4 + 0] = a.x; qs[t][i * 4 + 1] = a.y; qs[t][i * 4 + 2] = a.z; qs[t][i * 4 + 3] = a.w;
        ks[t][i * 4 + 0] = b.x; ks[t][i * 4 + 1] = b.y; ks[t][i * 4 + 2] = b.z; ks[t][i * 4 + 3] = b.w;
    }
    __syncthreads();
    int d = t >> 4, e = t & 15;
    float acc = 0.f;
    for (int j = 0; j < 256; j++) acc += qs[j][d] * ks[j][e];
    g_gpart[(h * 256 + t) * 128 + chunk] = acc;
    if (t < 16) {
        float s = 0.f;
        for (int j = 0; j < 256; j++) s += qs[j][t] * qs[j][t];
        g_nqpart[(h * 16 + t) * 128 + chunk] = s;
    } else if (t < 32) {
        int dd = t - 16;
        float s = 0.f;
        for (int j = 0; j < 256; j++) s += ks[j][dd] * ks[j][dd];
        g_nkpart[(h * 16 + dd) * 128 + chunk] = s;
    }
}

// ---------------- 3b) warp-per-row reduce of partials ----------------
__global__ void k_careduce() {
    int warp = threadIdx.x >> 5, lane = threadIdx.x & 31;
    int r = blockIdx.x * 8 + warp;   // 1152 rows
    const float* src;
    if (r < 1024) src = &g_gpart[r * 128];
    else if (r < 1088) src = &g_nqpart[(r - 1024) * 128];
    else src = &g_nkpart[(r - 1088) * 128];
    float s = src[lane] + src[lane + 32] + src[lane + 64] + src[lane + 96];
#pragma unroll
    for (int off = 16; off > 0; off >>= 1) s += __shfl_down_sync(0xffffffffu, s, off);
    if (lane == 0) {
        if (r < 1024) g_G[r] = s;
        else if (r < 1088) g_nq[r - 1024] = fmaxf(sqrtf(s), 1e-12f);
        else g_nk[r - 1088] = fmaxf(sqrtf(s), 1e-12f);
    }
}

// ---------------- 4) finalize channel attention softmax ----------------
__global__ void k_ca_fin(const float* __restrict__ temp) {
    int t = threadIdx.x;  // 64 threads
    int h = t >> 4, d = t & 15;
    float tp = __ldg(&temp[h]);
    float dq = g_nq[t];
    float row[16], mx = -1e30f;
#pragma unroll
    for (int e = 0; e < 16; e++) {
        row[e] = g_G[h * 256 + d * 16 + e] / (dq * g_nk[h * 16 + e]) * tp;
        mx = fmaxf(mx, row[e]);
    }
    float sum = 0.f;
#pragma unroll
    for (int e = 0; e < 16; e++) { row[e] = __expf(row[e] - mx); sum += row[e]; }
    float inv = 1.f / sum;
#pragma unroll
    for (int e = 0; e < 16; e++) g_A[h * 256 + d * 16 + e] = row[e] * inv;
}

// ---------------- 5) spatial attention, smem-tiled ----------------
__global__ void k_spatial(const float* __restrict__ qemb, const float* __restrict__ temp2,
                          const float* __restrict__ rpb) {
    extern __shared__ float4 smbuf[];
    float4* sk = smbuf;
    float4* sv = smbuf + 4 * SPP;
    int tid = threadIdx.x;
    int h = blockIdx.y;
    int z0 = (blockIdx.x >> 3) * 2, y0 = (blockIdx.x & 7) * 4;

    for (int idx = tid; idx < 3264; idx += 256) {
        int pos = idx >> 2, d4 = idx & 3;
        int hz = pos / 204;
        int rem = pos - hz * 204;
        int hy = rem / 34;
        int hx = rem - hy * 34;
        int gz = z0 + hz - 1, gy = y0 + hy - 1, gx = hx - 1;
        float4 kv = make_float4(0.f, 0.f, 0.f, 0.f);
        float4 vv = kv;
        if ((unsigned)(gz | gy | gx) < 32u) {
            int n2 = (gz * 32 + gy) * 32 + gx;
            size_t off = (size_t)(h * NTOT + n2) * 16 + d4 * 4;
            kv = *reinterpret_cast<const float4*>(g_qk + (size_t)REG + off);
            vv = *reinterpret_cast<const float4*>(g_qk + (size_t)2 * REG + off);
        }
        sk[d4 * SPP + pos] = kv;
        sv[d4 * SPP + pos] = vv;
    }

    int lx = tid & 31, ly = (tid >> 5) & 3, lz = tid >> 7;
    int gz = z0 + lz, gy = y0 + ly, gx = lx;
    int n = (gz * 32 + gy) * 32 + gx;

    float q[16];
    {
        const float4* qp = reinterpret_cast<const float4*>(g_qk + (size_t)(h * NTOT + n) * 16);
#pragma unroll
        for (int i = 0; i < 4; i++) {
            float4 v = qp[i];
            q[i * 4 + 0] = v.x; q[i * 4 + 1] = v.y; q[i * 4 + 2] = v.z; q[i * 4 + 3] = v.w;
        }
    }
    float ssq = 0.f;
#pragma unroll
    for (int d = 0; d < 16; d++) ssq += q[d] * q[d];
    float inv = 1.f / fmaxf(sqrtf(ssq), 1e-12f);
    float sp = log1pf(expf(__ldg(&temp2[h])));
    float qn[16];
#pragma unroll
    for (int d = 0; d < 16; d++) qn[d] = (q[d] * inv + __ldg(&qemb[h * 16 + d])) * sp;

    __syncthreads();

    int base = (lz + 1) * 204 + (ly + 1) * 34 + (lx + 1);
    float sc[27];
    float mx = -1e30f;
#pragma unroll
    for (int kk = 0; kk < 27; kk++) {
        int dz = kk / 9 - 1, dy = (kk / 3) % 3 - 1, dx = kk % 3 - 1;
        int bz = gz + dz, by = gy + dy, bx = gx + dx;
        float s = -1e30f;
        if ((unsigned)(bz | by | bx) < 32u) {
            int np = base + dz * 204 + dy * 34 + dx;
            float dot = 0.f;
#pragma unroll
            for (int d4 = 0; d4 < 4; d4++) {
                float4 kv = sk[d4 * SPP + np];
                dot += qn[d4 * 4 + 0] * kv.x + qn[d4 * 4 + 1] * kv.y +
                       qn[d4 * 4 + 2] * kv.z + qn[d4 * 4 + 3] * kv.w;
            }
            s = dot + __ldg(&rpb[h * 27 + kk]);
        }
        sc[kk] = s;
        mx = fmaxf(mx, s);
    }
    float sum = 0.f;
#pragma unroll
    for (int kk = 0; kk < 27; kk++) { sc[kk] = __expf(sc[kk] - mx); sum += sc[kk]; }
    float rinv = 1.f / sum;
    float out[16];
#pragma unroll
    for (int d = 0; d < 16; d++) out[d] = 0.f;
#pragma unroll
    for (int kk = 0; kk < 27; kk++) {
        int dz = kk / 9 - 1, dy = (kk / 3) % 3 - 1, dx = kk % 3 - 1;
        int bz = gz + dz, by = gy + dy, bx = gx + dx;
        if ((unsigned)(bz | by | bx) < 32u) {
            int np = base + dz * 204 + dy * 34 + dx;
            float p = sc[kk] * rinv;
#pragma unroll
            for (int d4 = 0; d4 < 4; d4++) {
                float4 vv = sv[d4 * SPP + np];
                out[d4 * 4 + 0] += p * vv.x; out[d4 * 4 + 1] += p * vv.y;
                out[d4 * 4 + 2] += p * vv.z; out[d4 * 4 + 3] += p * vv.w;
            }
        }
    }
    float4* dst = reinterpret_cast<float4*>(g_sa + (size_t)(h * NTOT + n) * 16);
#pragma unroll
    for (int i = 0; i < 4; i++)
        dst[i] = make_float4(out[i * 4], out[i * 4 + 1], out[i * 4 + 2], out[i * 4 + 3]);
}

// ---------------- 6) combine ----------------
__global__ void k_combine(const float* __restrict__ x, const float* __restrict__ gamma,
                          const float* __restrict__ w1, const float* __restrict__ b1,
                          const float* __restrict__ w2, const float* __restrict__ b2) {
    __shared__ float w1s[2048];
    __shared__ float w2s[2048];
    __shared__ float As[1024];
    __shared__ float b1s[32];
    __shared__ float b2s[32];
    int t = threadIdx.x;
    for (int i = t; i < 2048; i += 256) { w1s[i] = w1[i]; w2s[i] = w2[i]; }
    for (int i = t; i < 1024; i += 256) As[i] = g_A[i];
    if (t < 32) { b1s[t] = b1[t]; b2s[t] = b2[t]; }
    __syncthreads();
    int n = blockIdx.x * 256 + t;
    {
        float xsa[64];
        const float4* sp4 = reinterpret_cast<const float4*>(g_sa + (size_t)n * 64);
#pragma unroll
        for (int i = 0; i < 16; i++) {
            float4 v = sp4[i];
            xsa[i * 4 + 0] = v.x; xsa[i * 4 + 1] = v.y; xsa[i * 4 + 2] = v.z; xsa[i * 4 + 3] = v.w;
        }
        for (int o = 0; o < 32; o++) {
            float a = b1s[o];
#pragma unroll
            for (int c = 0; c < 64; c++) a += xsa[c] * w1s[o * 64 + c];
            g_skip[o * NTOT + n] = x[o * NTOT + n] + __ldg(&gamma[o]) * a;
        }
    }
    {
        float xca[64];
#pragma unroll
        for (int h = 0; h < 4; h++) {
            float vc[16];
#pragma unroll
            for (int e = 0; e < 16; e++)
                vc[e] = g_qk[(size_t)3 * REG + (h * 16 + e) * NTOT + n];
#pragma unroll
            for (int d = 0; d < 16; d++) {
                float a = 0.f;
#pragma unroll
                for (int e = 0; e < 16; e++) a += As[h * 256 + d * 16 + e] * vc[e];
                xca[h * 16 + d] = a;
            }
        }
        for (int o = 0; o < 32; o++) {
            float a = b2s[o];
#pragma unroll
            for (int c = 0; c < 64; c++) a += xca[c] * w2s[o * 64 + c];
            g_skip[(32 + o) * NTOT + n] = x[(32 + o) * NTOT + n] + __ldg(&gamma[32 + o]) * a;
        }
    }
}

// ---------------- 7) conv3d 3x3x3, 8 points x 8 ochannels per thread -----------
// grid (16, 8): tiles z0=(t>>1)*4 y0=(t&1)*16, 8 o-groups of 8.
// dyn smem: xs 4*3672, ws 864 float2, sc/sh 8, red 128
__global__ void k_conv3(const float* __restrict__ in, const float* __restrict__ w,
                        const float* __restrict__ bias, float* __restrict__ out,
                        const float* __restrict__ bn_g, const float* __restrict__ bn_be,
                        int fuse) {
    extern __shared__ float dsm[];
    float* xs = dsm;                         // 14688
    float2* ws = (float2*)(dsm + 14688);     // 864 float2
    float* sc4 = dsm + 14688 + 1728;         // 4
    float* sh4 = sc4 + 4;                    // 4
    float* red_s = sh4 + 4;                  // 8 warps x 8 o
    float* red_q = red_s + 64;               // 64

    int tid = threadIdx.x;
    int tile = blockIdx.x;
    int z0 = (tile >> 1) * 4, y0 = (tile & 1) * 16;
    int obase = blockIdx.y * 8;

    int pb[8], nout[8];
#pragma unroll
    for (int j = 0; j < 8; j++) {
        int idx = tid + j * 256;
        int z = idx >> 9, y = (idx >> 5) & 15, xx = idx & 31;
        pb[j] = z * 612 + y * 34 + xx;            // halo base; tap koff adds dz*612+dy*34+dx
        nout[j] = (z0 + z) * 1024 + (y0 + y) * 32 + xx;
    }
    unsigned long long acc[8][4];
#pragma unroll
    for (int o = 0; o < 8; o++)
#pragma unroll
        for (int p = 0; p < 4; p++) acc[o][p] = 0ull;

    for (int ci = 0; ci < 16; ci++) {
        int ibase = ci * 4;
        if (fuse && tid < 4) {
            int c = ibase + tid;
            float sc = g_bn[64 + c] * bn_g[c];
            sc4[tid] = sc;
            sh4[tid] = bn_be[c] - g_bn[c] * sc;
        }
        __syncthreads();
        for (int idx = tid; idx < 14688; idx += 256) {
            int ii = idx / 3672;
            int r1 = idx - ii * 3672;
            int zz = r1 / 612;
            int r2 = r1 - zz * 612;
            int yy = r2 / 34;
            int xxx = r2 - yy * 34;
            int ga0 = z0 + zz - 1, ga1 = y0 + yy - 1, ga2 = xxx - 1;
            float v = 0.f;
            if ((unsigned)(ga0 | ga1 | ga2) < 32u) {
                v = in[(ibase + ii) * NTOT + ga0 * 1024 + ga1 * 32 + ga2];
                if (fuse) {
                    float t = v * sc4[ii] + sh4[ii];
                    v = t > 0.f ? t : 0.01f * t;
                }
            }
            xs[idx] = v;
        }
        for (int idx = tid; idx < 864; idx += 256) {
            int o = idx / 108;
            int r = idx - o * 108;
            int ii = r / 27, kk = r - ii * 27;
            float wv = w[(obase + o) * 1728 + (ibase + ii) * 27 + kk];
            ws[idx] = make_float2(wv, wv);
        }
        __syncthreads();
#pragma unroll
        for (int ii = 0; ii < 4; ii++) {
#pragma unroll
            for (int kk = 0; kk < 27; kk++) {
                int koff = (kk / 9) * 612 + ((kk / 3) % 3) * 34 + (kk % 3);
                int xb = ii * 3672 + koff;
                unsigned long long x01 = pack2(xs[xb + pb[0]], xs[xb + pb[1]]);
                unsigned long long x23 = pack2(xs[xb + pb[2]], xs[xb + pb[3]]);
                unsigned long long x45 = pack2(xs[xb + pb[4]], xs[xb + pb[5]]);
                unsigned long long x67 = pack2(xs[xb + pb[6]], xs[xb + pb[7]]);
#pragma unroll
                for (int o = 0; o < 8; o++) {
                    unsigned long long wv =
                        *reinterpret_cast<const unsigned long long*>(&ws[o * 108 + ii * 27 + kk]);
                    ffma2(acc[o][0], x01, wv);
                    ffma2(acc[o][1], x23, wv);
                    ffma2(acc[o][2], x45, wv);
                    ffma2(acc[o][3], x67, wv);
                }
            }
        }
        __syncthreads();
    }
    int lane = tid & 31, warp = tid >> 5;
#pragma unroll
    for (int o = 0; o < 8; o++) {
        float bo = __ldg(&bias[obase + o]);
        float f[8];
#pragma unroll
        for (int p = 0; p < 4; p++) unpack2(acc[o][p], f[p * 2], f[p * 2 + 1]);
        size_t ob = (size_t)(obase + o) * NTOT;
        float s = 0.f, qq = 0.f;
#pragma unroll
        for (int j = 0; j < 8; j++) {
            f[j] += bo;
            out[ob + nout[j]] = f[j];
            s += f[j];
            qq += f[j] * f[j];
        }
#pragma unroll
        for (int off = 16; off > 0; off >>= 1) {
            s += __shfl_down_sync(0xffffffffu, s, off);
            qq += __shfl_down_sync(0xffffffffu, qq, off);
        }
        if (lane == 0) { red_s[warp * 8 + o] = s; red_q[warp * 8 + o] = qq; }
    }
    __syncthreads();
    if (tid < 8) {
        float s = 0.f, qq = 0.f;
#pragma unroll
        for (int wp = 0; wp < 8; wp++) { s += red_s[wp * 8 + tid]; qq += red_q[wp * 8 + tid]; }
        g_bnps[(obase + tid) * 16 + blockIdx.x] = s;
        g_bnpq[(obase + tid) * 16 + blockIdx.x] = qq;
    }
}

// ---------------- 8) finalize batchnorm stats ----------------
__global__ void k_bnfin() {
    int c = threadIdx.x;  // 64
    float s = 0.f, qq = 0.f;
#pragma unroll
    for (int j = 0; j < 16; j++) { s += g_bnps[c * 16 + j]; qq += g_bnpq[c * 16 + j]; }
    float m = s * (1.f / NTOT);
    float var = qq * (1.f / NTOT) - m * m;
    g_bn[c] = m;
    g_bn[64 + c] = rsqrtf(var + 1e-5f);
}

// ---------------- 9) bn apply + residual + leaky relu ----------------
__global__ void k_bnapply(const float* __restrict__ t, const float* __restrict__ g,
                          const float* __restrict__ be, const float* __restrict__ res,
                          float* __restrict__ out) {
    int idx = blockIdx.x * 256 + threadIdx.x;
    int c = idx >> 15;
    float v = (t[idx] - g_bn[c]) * g_bn[64 + c] * __ldg(&g[c]) + __ldg(&be[c]) + res[idx];
    out[idx] = v > 0.f ? v : 0.01f * v;
}

// ---------------- 10) final: fused bn+res+lrelu then skip + conv1x1 ------------
__global__ void k_final(const float* __restrict__ skip, const float* __restrict__ t4,
                        const float* __restrict__ res, const float* __restrict__ cw,
                        const float* __restrict__ cb, const float* __restrict__ bn_g,
                        const float* __restrict__ bn_be, float* __restrict__ out) {
    __shared__ float ws[4096];
    __shared__ float scs[64];
    __shared__ float shs[64];
    int t = threadIdx.x;
    for (int i = t; i < 4096; i += 256) ws[i] = cw[i];
    if (t < 64) {
        float sc = g_bn[64 + t] * bn_g[t];
        scs[t] = sc;
        shs[t] = bn_be[t] - g_bn[t] * sc;
    }
    __syncthreads();
    int n = blockIdx.x * 256 + t;
    float yv[64];
#pragma unroll
    for (int i = 0; i < 64; i++) {
        float v = t4[i * NTOT + n] * scs[i] + shs[i] + res[i * NTOT + n];
        yv[i] = v > 0.f ? v : 0.01f * v;
    }
    for (int c = 0; c < 64; c++) {
        float a = __ldg(&cb[c]);
#pragma unroll
        for (int i = 0; i < 64; i++) a += ws[c * 64 + i] * yv[i];
        out[c * NTOT + n] = skip[c * NTOT + n] + a;
    }
}

// ---------------- launch ----------------
extern "C" void kernel_launch(void* const* d_in, const int* in_sizes, int n_in,
                              void* d_out, int out_size) {
    const float* x      = (const float*)d_in[0];
    const float* ln_g   = (const float*)d_in[1];
    const float* ln_b   = (const float*)d_in[2];
    const float* gamma  = (const float*)d_in[3];
    const float* qkvv_w = (const float*)d_in[4];
    const float* temp   = (const float*)d_in[5];
    const float* temp2  = (const float*)d_in[6];
    const float* rpb    = (const float*)d_in[7];
    const float* qemb   = (const float*)d_in[8];
    const float* op1_w  = (const float*)d_in[9];
    const float* op1_b  = (const float*)d_in[10];
    const float* op2_w  = (const float*)d_in[11];
    const float* op2_b  = (const float*)d_in[12];
    const float* c51_w1 = (const float*)d_in[13];
    const float* c51_b1 = (const float*)d_in[14];
    const float* c51_g1 = (const float*)d_in[15];
    const float* c51_be1= (const float*)d_in[16];
    const float* c51_w2 = (const float*)d_in[17];
    const float* c51_b2 = (const float*)d_in[18];
    const float* c51_g2 = (const float*)d_in[19];
    const float* c51_be2= (const float*)d_in[20];
    const float* c52_w1 = (const float*)d_in[21];
    const float* c52_b1 = (const float*)d_in[22];
    const float* c52_g1 = (const float*)d_in[23];
    const float* c52_be1= (const float*)d_in[24];
    const float* c52_w2 = (const float*)d_in[25];
    const float* c52_b2 = (const float*)d_in[26];
    const float* c52_g2 = (const float*)d_in[27];
    const float* c52_be2= (const float*)d_in[28];
    const float* c8_w   = (const float*)d_in[29];
    const float* c8_b   = (const float*)d_in[30];
    float* out = (float*)d_out;

    float *p_skip, *p_t1, *p_t2, *p_t3;
    cudaGetSymbolAddress((void**)&p_skip, g_skip);
    cudaGetSymbolAddress((void**)&p_t1, g_t1);
    cudaGetSymbolAddress((void**)&p_t2, g_t2);
    cudaGetSymbolAddress((void**)&p_t3, g_t3);

    const int SMEM_SP = 8 * SPP * 16;                 // 104576 B
    const int SMEM_CV = (14688 + 1728 + 8 + 128) * 4; // 66208 B
    cudaFuncSetAttribute(k_spatial, cudaFuncAttributeMaxDynamicSharedMemorySize, SMEM_SP);
    cudaFuncSetAttribute(k_conv3, cudaFuncAttributeMaxDynamicSharedMemorySize, SMEM_CV);

    k_layernorm<<<128, 256>>>(x, ln_g, ln_b);
    k_qkvv<<<dim3(32, 16), 256>>>(qkvv_w);
    k_gram<<<dim3(128, 4), 256>>>();
    k_careduce<<<144, 256>>>();
    k_ca_fin<<<1, 64>>>(temp);
    k_spatial<<<dim3(128, 4), 256, SMEM_SP>>>(qemb, temp2, rpb);
    k_combine<<<128, 256>>>(x, gamma, op1_w, op1_b, op2_w, op2_b);

    // resblock 1
    k_conv3<<<dim3(16, 8), 256, SMEM_CV>>>(p_skip, c51_w1, c51_b1, p_t1, nullptr, nullptr, 0);
    k_bnfin<<<1, 64>>>();
    k_conv3<<<dim3(16, 8), 256, SMEM_CV>>>(p_t1, c51_w2, c51_b2, p_t2, c51_g1, c51_be1, 1);
    k_bnfin<<<1, 64>>>();
    k_bnapply<<<8192, 256>>>(p_t2, c51_g2, c51_be2, p_skip, p_t3);

    // resblock 2
    k_conv3<<<dim3(16, 8), 256, SMEM_CV>>>(p_t3, c52_w1, c52_b1, p_t1, nullptr, nullptr, 0);
    k_bnfin<<<1, 64>>>();
    k_conv3<<<dim3(16, 8), 256, SMEM_CV>>>(p_t1, c52_w2, c52_b2, p_t2, c52_g1, c52_be1, 1);
    k_bnfin<<<1, 64>>>();

    k_final<<<128, 256>>>(p_skip, p_t2, p_t3, c8_w, c8_b, c52_g2, c52_be2, out);
}